// round 1
// baseline (speedup 1.0000x reference)
#include <cuda_runtime.h>
#include <math.h>

#define Bx   8
#define Sx   2048
#define Fx   512
#define Hx   8
#define Mh   64
#define HMx  512

// Scratch (allocation-free rule: __device__ globals)
__device__ float g_q[(size_t)Bx * Sx * HMx];
__device__ float g_k[(size_t)Bx * Sx * HMx];
__device__ float g_v[(size_t)Bx * Sx * HMx];
__device__ float g_m[(size_t)Bx * Sx * HMx];

// ---------------------------------------------------------------------------
// C[Mr,512] = A[Mr,512] @ W[512,512] + bias   (Mr = 16384, tiles 128x64x16)
// ---------------------------------------------------------------------------
__global__ void __launch_bounds__(256) gemm512_kernel(
    const float* __restrict__ A, const float* __restrict__ W,
    const float* __restrict__ bias, float* __restrict__ C)
{
    const int BM = 128, BN = 64, BK = 16;
    __shared__ float As[BK][BM];
    __shared__ float Bs[BK][BN];

    const int n0  = blockIdx.x * BN;
    const int m0  = blockIdx.y * BM;
    const int tid = threadIdx.x;
    const int tm  = tid >> 4;   // 0..15 -> 8 rows each
    const int tn  = tid & 15;   // 0..15 -> 4 cols each

    float acc[8][4];
#pragma unroll
    for (int i = 0; i < 8; i++)
#pragma unroll
        for (int j = 0; j < 4; j++) acc[i][j] = 0.f;

    for (int kb = 0; kb < 512; kb += BK) {
        // A tile: 128 rows x 16 cols = 512 float4, 2 per thread
#pragma unroll
        for (int i = 0; i < 2; i++) {
            int idx = tid + i * 256;          // 0..511
            int row = idx >> 2;
            int c4  = idx & 3;
            float4 a = *(const float4*)&A[(size_t)(m0 + row) * 512 + kb + c4 * 4];
            As[c4 * 4 + 0][row] = a.x;
            As[c4 * 4 + 1][row] = a.y;
            As[c4 * 4 + 2][row] = a.z;
            As[c4 * 4 + 3][row] = a.w;
        }
        // B tile: 16 rows x 64 cols = 256 float4, 1 per thread
        {
            int row = tid >> 4;
            int c4  = tid & 15;
            *(float4*)&Bs[row][c4 * 4] =
                *(const float4*)&W[(size_t)(kb + row) * 512 + n0 + c4 * 4];
        }
        __syncthreads();

#pragma unroll
        for (int k = 0; k < BK; k++) {
            float4 a0 = *(const float4*)&As[k][tm * 8];
            float4 a1 = *(const float4*)&As[k][tm * 8 + 4];
            float4 bb = *(const float4*)&Bs[k][tn * 4];
            float a[8] = {a0.x, a0.y, a0.z, a0.w, a1.x, a1.y, a1.z, a1.w};
            float b[4] = {bb.x, bb.y, bb.z, bb.w};
#pragma unroll
            for (int i = 0; i < 8; i++)
#pragma unroll
                for (int j = 0; j < 4; j++) acc[i][j] += a[i] * b[j];
        }
        __syncthreads();
    }

    float4 bia = *(const float4*)&bias[n0 + tn * 4];
#pragma unroll
    for (int i = 0; i < 8; i++) {
        float4 o;
        o.x = acc[i][0] + bia.x;
        o.y = acc[i][1] + bia.y;
        o.z = acc[i][2] + bia.z;
        o.w = acc[i][3] + bia.w;
        *(float4*)&C[(size_t)(m0 + tm * 8 + i) * 512 + n0 + tn * 4] = o;
    }
}

// ---------------------------------------------------------------------------
// Flash-style masked attention. 1 thread = 1 query row. Grid (S/128, B, H).
// smem: K chunk [64x64], V chunk [64x64], score rows [128][65]
// ---------------------------------------------------------------------------
__global__ void __launch_bounds__(128, 3) attn_kernel(
    const float* __restrict__ qg, const float* __restrict__ kg,
    const float* __restrict__ vg, const float* __restrict__ mask,
    float* __restrict__ msgs)
{
    extern __shared__ float sh[];
    float* Ks = sh;            // 4096 floats
    float* Vs = sh + 4096;     // 4096 floats
    float* Ss = sh + 8192;     // 128*65 floats

    const int h   = blockIdx.z;
    const int b   = blockIdx.y;
    const int s0  = blockIdx.x * 128;
    const int tid = threadIdx.x;
    const int srow = s0 + tid;
    const float scale = 0.125f;   // rsqrt(64)

    // q row (pre-scaled) into registers
    float qv[64];
    {
        const float4* qp = (const float4*)(qg + ((size_t)b * Sx + srow) * HMx + h * Mh);
#pragma unroll
        for (int i = 0; i < 16; i++) {
            float4 t4 = qp[i];
            qv[4 * i + 0] = t4.x * scale;
            qv[4 * i + 1] = t4.y * scale;
            qv[4 * i + 2] = t4.z * scale;
            qv[4 * i + 3] = t4.w * scale;
        }
    }

    float acc[64];
#pragma unroll
    for (int d = 0; d < 64; d++) acc[d] = 0.f;
    float mmax = -INFINITY, lsum = 0.f;

    float* ss = Ss + tid * 65;
    const float* mrowbase = mask + ((size_t)b * Sx + srow) * Sx;

    for (int t0 = 0; t0 < Sx; t0 += 64) {
        const float* kbase = kg + ((size_t)b * Sx + t0) * HMx + h * Mh;
        const float* vbase = vg + ((size_t)b * Sx + t0) * HMx + h * Mh;
        // cooperative load of K,V chunk (coalesced 512B per j-step)
#pragma unroll
        for (int j = 0; j < 8; j++) {
            int lin = j * 128 + tid;
            int row = lin >> 4;
            int c4  = lin & 15;
            ((float4*)Ks)[lin] = *(const float4*)(kbase + row * HMx + c4 * 4);
            ((float4*)Vs)[lin] = *(const float4*)(vbase + row * HMx + c4 * 4);
        }
        __syncthreads();

        // pass 1: scores + mask -> smem, track chunk max
        float cmax = -INFINITY;
        const float4* mrow4 = (const float4*)(mrowbase + t0);
#pragma unroll 1
        for (int t4 = 0; t4 < 16; t4++) {
            float4 mk = mrow4[t4];
            float mka[4] = {mk.x, mk.y, mk.z, mk.w};
#pragma unroll
            for (int u = 0; u < 4; u++) {
                int t = t4 * 4 + u;
                const float4* kr = (const float4*)(Ks + t * 64);
                float s = 0.f;
#pragma unroll
                for (int i = 0; i < 16; i++) {
                    float4 kk = kr[i];
                    s += qv[4 * i + 0] * kk.x + qv[4 * i + 1] * kk.y
                       + qv[4 * i + 2] * kk.z + qv[4 * i + 3] * kk.w;
                }
                // masked -> -inf: exp underflows to exactly 0 (matches
                // reference: exp(score - 1e9 - max) == 0 in fp32, and the
                // final *mask zeroing is reproduced by lsum==0 guard)
                s = (mka[u] > 0.5f) ? s : -INFINITY;
                ss[t] = s;
                cmax = fmaxf(cmax, s);
            }
        }

        float newm = fmaxf(mmax, cmax);
        if (newm > -INFINITY) {
            float alpha = __expf(mmax - newm);   // mmax=-inf -> 0, acc already 0
            lsum *= alpha;
#pragma unroll
            for (int d = 0; d < 64; d++) acc[d] *= alpha;
#pragma unroll 2
            for (int t = 0; t < 64; t++) {
                float p = __expf(ss[t] - newm);  // -inf -> exactly 0
                lsum += p;
                const float4* vr = (const float4*)(Vs + t * 64);
#pragma unroll
                for (int i = 0; i < 16; i++) {
                    float4 vv = vr[i];
                    acc[4 * i + 0] += p * vv.x;
                    acc[4 * i + 1] += p * vv.y;
                    acc[4 * i + 2] += p * vv.z;
                    acc[4 * i + 3] += p * vv.w;
                }
            }
            mmax = newm;
        }
        __syncthreads();
    }

    float inv = (lsum > 0.f) ? (1.0f / lsum) : 0.f;  // fully-masked row -> 0
    float* orow = msgs + ((size_t)b * Sx + srow) * HMx + h * Mh;
#pragma unroll
    for (int i = 0; i < 16; i++) {
        float4 o;
        o.x = acc[4 * i + 0] * inv;
        o.y = acc[4 * i + 1] * inv;
        o.z = acc[4 * i + 2] * inv;
        o.w = acc[4 * i + 3] * inv;
        ((float4*)orow)[i] = o;
    }
}

// ---------------------------------------------------------------------------
extern "C" void kernel_launch(void* const* d_in, const int* in_sizes, int n_in,
                              void* d_out, int out_size)
{
    (void)in_sizes; (void)n_in; (void)out_size;
    const float* x    = (const float*)d_in[0];
    const float* mask = (const float*)d_in[1];
    const float* Wq   = (const float*)d_in[2];
    const float* Wk   = (const float*)d_in[3];
    const float* Wv   = (const float*)d_in[4];
    const float* bq   = (const float*)d_in[5];
    const float* bk   = (const float*)d_in[6];
    const float* bv   = (const float*)d_in[7];
    const float* Wo   = (const float*)d_in[8];
    const float* bo   = (const float*)d_in[9];
    float* out = (float*)d_out;

    float *qp, *kp, *vp, *mp;
    cudaGetSymbolAddress((void**)&qp, g_q);
    cudaGetSymbolAddress((void**)&kp, g_k);
    cudaGetSymbolAddress((void**)&vp, g_v);
    cudaGetSymbolAddress((void**)&mp, g_m);

    dim3 gg(512 / 64, (Bx * Sx) / 128);   // (8, 128)
    gemm512_kernel<<<gg, 256>>>(x, Wq, bq, qp);
    gemm512_kernel<<<gg, 256>>>(x, Wk, bk, kp);
    gemm512_kernel<<<gg, 256>>>(x, Wv, bv, vp);

    int smem = (4096 + 4096 + 128 * 65) * (int)sizeof(float);  // 66,048 B
    cudaFuncSetAttribute(attn_kernel, cudaFuncAttributeMaxDynamicSharedMemorySize, smem);
    dim3 ga(Sx / 128, Bx, Hx);            // (16, 8, 8)
    attn_kernel<<<ga, 128, smem>>>(qp, kp, vp, mask, mp);

    gemm512_kernel<<<gg, 256>>>(mp, Wo, bo, out);
}

// round 2
// speedup vs baseline: 1.7631x; 1.7631x over previous
#include <cuda_runtime.h>
#include <math.h>
#include <stdint.h>

#define Bx   8
#define Sx   2048
#define Fx   512
#define Hx   8
#define Mh   64
#define HMx  512

// Scratch (allocation-free rule: __device__ globals)
__device__ float g_q[(size_t)Bx * Sx * HMx];
__device__ float g_k[(size_t)Bx * Sx * HMx];
__device__ float g_v[(size_t)Bx * Sx * HMx];
__device__ float g_m[(size_t)Bx * Sx * HMx];

// ---------------------------------------------------------------------------
// fp32 GEMM: C[16384,512] = A @ W + bias (tiles 128x64x16) — unchanged from R0
// ---------------------------------------------------------------------------
__global__ void __launch_bounds__(256) gemm512_kernel(
    const float* __restrict__ A, const float* __restrict__ W,
    const float* __restrict__ bias, float* __restrict__ C)
{
    const int BM = 128, BN = 64, BK = 16;
    __shared__ float As[BK][BM];
    __shared__ float Bs[BK][BN];

    const int n0  = blockIdx.x * BN;
    const int m0  = blockIdx.y * BM;
    const int tid = threadIdx.x;
    const int tm  = tid >> 4;
    const int tn  = tid & 15;

    float acc[8][4];
#pragma unroll
    for (int i = 0; i < 8; i++)
#pragma unroll
        for (int j = 0; j < 4; j++) acc[i][j] = 0.f;

    for (int kb = 0; kb < 512; kb += BK) {
#pragma unroll
        for (int i = 0; i < 2; i++) {
            int idx = tid + i * 256;
            int row = idx >> 2;
            int c4  = idx & 3;
            float4 a = *(const float4*)&A[(size_t)(m0 + row) * 512 + kb + c4 * 4];
            As[c4 * 4 + 0][row] = a.x;
            As[c4 * 4 + 1][row] = a.y;
            As[c4 * 4 + 2][row] = a.z;
            As[c4 * 4 + 3][row] = a.w;
        }
        {
            int row = tid >> 4;
            int c4  = tid & 15;
            *(float4*)&Bs[row][c4 * 4] =
                *(const float4*)&W[(size_t)(kb + row) * 512 + n0 + c4 * 4];
        }
        __syncthreads();

#pragma unroll
        for (int k = 0; k < BK; k++) {
            float4 a0 = *(const float4*)&As[k][tm * 8];
            float4 a1 = *(const float4*)&As[k][tm * 8 + 4];
            float4 bb = *(const float4*)&Bs[k][tn * 4];
            float a[8] = {a0.x, a0.y, a0.z, a0.w, a1.x, a1.y, a1.z, a1.w};
            float b[4] = {bb.x, bb.y, bb.z, bb.w};
#pragma unroll
            for (int i = 0; i < 8; i++)
#pragma unroll
                for (int j = 0; j < 4; j++) acc[i][j] += a[i] * b[j];
        }
        __syncthreads();
    }

    float4 bia = *(const float4*)&bias[n0 + tn * 4];
#pragma unroll
    for (int i = 0; i < 8; i++) {
        float4 o;
        o.x = acc[i][0] + bia.x;
        o.y = acc[i][1] + bia.y;
        o.z = acc[i][2] + bia.z;
        o.w = acc[i][3] + bia.w;
        *(float4*)&C[(size_t)(m0 + tm * 8 + i) * 512 + n0 + tn * 4] = o;
    }
}

// ---------------------------------------------------------------------------
// tf32 tensor-core flash attention.
// Block = (64-query tile, b, h); 4 warps x 16 rows. Key chunks of 64.
// ---------------------------------------------------------------------------
__device__ __forceinline__ uint32_t f2tf(float x) {
    uint32_t r;
    asm("cvt.rna.tf32.f32 %0, %1;" : "=r"(r) : "f"(x));
    return r;
}

__device__ __forceinline__ void mma_tf32(float* c, const uint32_t* a,
                                         uint32_t b0, uint32_t b1) {
    asm volatile(
        "mma.sync.aligned.m16n8k8.row.col.f32.tf32.tf32.f32 "
        "{%0,%1,%2,%3}, {%4,%5,%6,%7}, {%8,%9}, {%0,%1,%2,%3};"
        : "+f"(c[0]), "+f"(c[1]), "+f"(c[2]), "+f"(c[3])
        : "r"(a[0]), "r"(a[1]), "r"(a[2]), "r"(a[3]), "r"(b0), "r"(b1));
}

#define QS_STRIDE 68   // conflict-free for 8-row x 4-col frag pattern
#define VS_STRIDE 72   // conflict-free for 4-row x 8-col frag pattern

__global__ void __launch_bounds__(128) attn_tc_kernel(
    const float* __restrict__ qg, const float* __restrict__ kg,
    const float* __restrict__ vg, const float* __restrict__ mask,
    float* __restrict__ msgs)
{
    extern __shared__ float sh[];
    float* Qs = sh;                       // 64 x 68 (reused as Ps after Q frags)
    float* Ks = sh + 64 * QS_STRIDE;      // 64 x 68
    float* Vs = sh + 2 * 64 * QS_STRIDE;  // 64 x 72

    const int h  = blockIdx.z;
    const int b  = blockIdx.y;
    const int q0 = blockIdx.x * 64;
    const int tid  = threadIdx.x;
    const int w    = tid >> 5;
    const int lane = tid & 31;
    const int qr   = lane >> 2;   // quad row 0..7
    const int qc   = lane & 3;    // quad col 0..3

    const int frow = tid >> 1;              // fill row 0..63
    const int fcol = (tid & 1) * 32;        // fill col 0 or 32

    // ---- Q tile -> smem (tf32, pre-scaled by rsqrt(64)) ----
    {
        const float4* src = (const float4*)(qg +
            ((size_t)b * Sx + q0 + frow) * HMx + h * Mh + fcol);
        float* dst = Qs + frow * QS_STRIDE + fcol;
#pragma unroll
        for (int i = 0; i < 8; i++) {
            float4 v = src[i];
            dst[4 * i + 0] = __uint_as_float(f2tf(v.x * 0.125f));
            dst[4 * i + 1] = __uint_as_float(f2tf(v.y * 0.125f));
            dst[4 * i + 2] = __uint_as_float(f2tf(v.z * 0.125f));
            dst[4 * i + 3] = __uint_as_float(f2tf(v.w * 0.125f));
        }
    }
    __syncwarp();   // warp w fills exactly its own 16-row band

    // ---- Q fragments into registers (persist whole kernel) ----
    const int rlo = w * 16 + qr;
    const int rhi = rlo + 8;
    uint32_t qa[8][4];
#pragma unroll
    for (int d = 0; d < 8; d++) {
        qa[d][0] = __float_as_uint(Qs[rlo * QS_STRIDE + d * 8 + qc]);
        qa[d][1] = __float_as_uint(Qs[rhi * QS_STRIDE + d * 8 + qc]);
        qa[d][2] = __float_as_uint(Qs[rlo * QS_STRIDE + d * 8 + qc + 4]);
        qa[d][3] = __float_as_uint(Qs[rhi * QS_STRIDE + d * 8 + qc + 4]);
    }
    __syncwarp();

    float o[8][4];
#pragma unroll
    for (int j = 0; j < 8; j++)
#pragma unroll
        for (int u = 0; u < 4; u++) o[j][u] = 0.f;
    float m_lo = -INFINITY, m_hi = -INFINITY;
    float l_lo = 0.f, l_hi = 0.f;

    const size_t mrow_lo = ((size_t)b * Sx + q0 + rlo) * Sx;
    const size_t mrow_hi = ((size_t)b * Sx + q0 + rhi) * Sx;

    for (int t0 = 0; t0 < Sx; t0 += 64) {
        __syncthreads();   // previous iteration's smem reads done
        // ---- K,V chunk -> smem (tf32) ----
        {
            const float4* ks = (const float4*)(kg +
                ((size_t)b * Sx + t0 + frow) * HMx + h * Mh + fcol);
            const float4* vs = (const float4*)(vg +
                ((size_t)b * Sx + t0 + frow) * HMx + h * Mh + fcol);
            float* kd = Ks + frow * QS_STRIDE + fcol;
            float* vd = Vs + frow * VS_STRIDE + fcol;
#pragma unroll
            for (int i = 0; i < 8; i++) {
                float4 kv = ks[i];
                kd[4 * i + 0] = __uint_as_float(f2tf(kv.x));
                kd[4 * i + 1] = __uint_as_float(f2tf(kv.y));
                kd[4 * i + 2] = __uint_as_float(f2tf(kv.z));
                kd[4 * i + 3] = __uint_as_float(f2tf(kv.w));
                float4 vv = vs[i];
                vd[4 * i + 0] = __uint_as_float(f2tf(vv.x));
                vd[4 * i + 1] = __uint_as_float(f2tf(vv.y));
                vd[4 * i + 2] = __uint_as_float(f2tf(vv.z));
                vd[4 * i + 3] = __uint_as_float(f2tf(vv.w));
            }
        }
        __syncthreads();

        // ---- S = Q K^T (16x64 per warp) ----
        float s[8][4];
#pragma unroll
        for (int j = 0; j < 8; j++)
#pragma unroll
            for (int u = 0; u < 4; u++) s[j][u] = 0.f;
#pragma unroll
        for (int d = 0; d < 8; d++) {
#pragma unroll
            for (int j = 0; j < 8; j++) {
                uint32_t b0 = __float_as_uint(Ks[(j * 8 + qr) * QS_STRIDE + d * 8 + qc]);
                uint32_t b1 = __float_as_uint(Ks[(j * 8 + qr) * QS_STRIDE + d * 8 + qc + 4]);
                mma_tf32(s[j], qa[d], b0, b1);
            }
        }

        // ---- mask + row max ----
        float rmax_lo = -INFINITY, rmax_hi = -INFINITY;
#pragma unroll
        for (int j = 0; j < 8; j++) {
            int col = t0 + j * 8 + 2 * qc;
            float2 ml = *(const float2*)(mask + mrow_lo + col);
            float2 mh = *(const float2*)(mask + mrow_hi + col);
            s[j][0] = (ml.x > 0.5f) ? s[j][0] : -INFINITY;
            s[j][1] = (ml.y > 0.5f) ? s[j][1] : -INFINITY;
            s[j][2] = (mh.x > 0.5f) ? s[j][2] : -INFINITY;
            s[j][3] = (mh.y > 0.5f) ? s[j][3] : -INFINITY;
            rmax_lo = fmaxf(rmax_lo, fmaxf(s[j][0], s[j][1]));
            rmax_hi = fmaxf(rmax_hi, fmaxf(s[j][2], s[j][3]));
        }
        rmax_lo = fmaxf(rmax_lo, __shfl_xor_sync(0xffffffff, rmax_lo, 1));
        rmax_lo = fmaxf(rmax_lo, __shfl_xor_sync(0xffffffff, rmax_lo, 2));
        rmax_hi = fmaxf(rmax_hi, __shfl_xor_sync(0xffffffff, rmax_hi, 1));
        rmax_hi = fmaxf(rmax_hi, __shfl_xor_sync(0xffffffff, rmax_hi, 2));

        float mn_lo = fmaxf(m_lo, rmax_lo);
        float mn_hi = fmaxf(m_hi, rmax_hi);
        float safe_lo = (mn_lo > -INFINITY) ? mn_lo : 0.f;
        float safe_hi = (mn_hi > -INFINITY) ? mn_hi : 0.f;
        float al = __expf(m_lo - safe_lo);   // -inf -> 0
        float ah = __expf(m_hi - safe_hi);

        // ---- P = exp(S - m), row sums ----
        float rs_lo = 0.f, rs_hi = 0.f;
#pragma unroll
        for (int j = 0; j < 8; j++) {
            s[j][0] = __expf(s[j][0] - safe_lo);
            s[j][1] = __expf(s[j][1] - safe_lo);
            s[j][2] = __expf(s[j][2] - safe_hi);
            s[j][3] = __expf(s[j][3] - safe_hi);
            rs_lo += s[j][0] + s[j][1];
            rs_hi += s[j][2] + s[j][3];
        }
        rs_lo += __shfl_xor_sync(0xffffffff, rs_lo, 1);
        rs_lo += __shfl_xor_sync(0xffffffff, rs_lo, 2);
        rs_hi += __shfl_xor_sync(0xffffffff, rs_hi, 1);
        rs_hi += __shfl_xor_sync(0xffffffff, rs_hi, 2);

        l_lo = l_lo * al + rs_lo;
        l_hi = l_hi * ah + rs_hi;
        m_lo = mn_lo;
        m_hi = mn_hi;

        // ---- rescale O, store P (tf32) into warp-private Ps band ----
#pragma unroll
        for (int j = 0; j < 8; j++) {
            o[j][0] *= al; o[j][1] *= al;
            o[j][2] *= ah; o[j][3] *= ah;
            float2 plo, phi;
            plo.x = __uint_as_float(f2tf(s[j][0]));
            plo.y = __uint_as_float(f2tf(s[j][1]));
            phi.x = __uint_as_float(f2tf(s[j][2]));
            phi.y = __uint_as_float(f2tf(s[j][3]));
            *(float2*)(Qs + rlo * QS_STRIDE + j * 8 + 2 * qc) = plo;
            *(float2*)(Qs + rhi * QS_STRIDE + j * 8 + 2 * qc) = phi;
        }
        __syncwarp();

        // ---- O += P V ----
#pragma unroll
        for (int kc = 0; kc < 8; kc++) {
            uint32_t a[4];
            a[0] = __float_as_uint(Qs[rlo * QS_STRIDE + kc * 8 + qc]);
            a[1] = __float_as_uint(Qs[rhi * QS_STRIDE + kc * 8 + qc]);
            a[2] = __float_as_uint(Qs[rlo * QS_STRIDE + kc * 8 + qc + 4]);
            a[3] = __float_as_uint(Qs[rhi * QS_STRIDE + kc * 8 + qc + 4]);
#pragma unroll
            for (int j = 0; j < 8; j++) {
                uint32_t b0 = __float_as_uint(Vs[(kc * 8 + qc) * VS_STRIDE + j * 8 + qr]);
                uint32_t b1 = __float_as_uint(Vs[(kc * 8 + qc + 4) * VS_STRIDE + j * 8 + qr]);
                mma_tf32(o[j], a, b0, b1);
            }
        }
    }

    // ---- epilogue: normalize, fully-masked rows -> 0 ----
    float il_lo = (l_lo > 0.f) ? (1.0f / l_lo) : 0.f;
    float il_hi = (l_hi > 0.f) ? (1.0f / l_hi) : 0.f;
    float* out_lo = msgs + ((size_t)b * Sx + q0 + rlo) * HMx + h * Mh;
    float* out_hi = msgs + ((size_t)b * Sx + q0 + rhi) * HMx + h * Mh;
#pragma unroll
    for (int j = 0; j < 8; j++) {
        float2 vlo, vhi;
        vlo.x = o[j][0] * il_lo; vlo.y = o[j][1] * il_lo;
        vhi.x = o[j][2] * il_hi; vhi.y = o[j][3] * il_hi;
        *(float2*)(out_lo + j * 8 + 2 * qc) = vlo;
        *(float2*)(out_hi + j * 8 + 2 * qc) = vhi;
    }
}

// ---------------------------------------------------------------------------
extern "C" void kernel_launch(void* const* d_in, const int* in_sizes, int n_in,
                              void* d_out, int out_size)
{
    (void)in_sizes; (void)n_in; (void)out_size;
    const float* x    = (const float*)d_in[0];
    const float* mask = (const float*)d_in[1];
    const float* Wq   = (const float*)d_in[2];
    const float* Wk   = (const float*)d_in[3];
    const float* Wv   = (const float*)d_in[4];
    const float* bq   = (const float*)d_in[5];
    const float* bk   = (const float*)d_in[6];
    const float* bv   = (const float*)d_in[7];
    const float* Wo   = (const float*)d_in[8];
    const float* bo   = (const float*)d_in[9];
    float* out = (float*)d_out;

    float *qp, *kp, *vp, *mp;
    cudaGetSymbolAddress((void**)&qp, g_q);
    cudaGetSymbolAddress((void**)&kp, g_k);
    cudaGetSymbolAddress((void**)&vp, g_v);
    cudaGetSymbolAddress((void**)&mp, g_m);

    dim3 gg(512 / 64, (Bx * Sx) / 128);
    gemm512_kernel<<<gg, 256>>>(x, Wq, bq, qp);
    gemm512_kernel<<<gg, 256>>>(x, Wk, bk, kp);
    gemm512_kernel<<<gg, 256>>>(x, Wv, bv, vp);

    int smem = (2 * 64 * QS_STRIDE + 64 * VS_STRIDE) * (int)sizeof(float); // 53248
    cudaFuncSetAttribute(attn_tc_kernel,
                         cudaFuncAttributeMaxDynamicSharedMemorySize, smem);
    dim3 ga(Sx / 64, Bx, Hx);   // (32, 8, 8)
    attn_tc_kernel<<<ga, 128, smem>>>(qp, kp, vp, mask, mp);

    gemm512_kernel<<<gg, 256>>>(mp, Wo, bo, out);
}

// round 3
// speedup vs baseline: 1.9021x; 1.0788x over previous
#include <cuda_runtime.h>
#include <math.h>
#include <stdint.h>

#define Bx   8
#define Sx   2048
#define Fx   512
#define Hx   8
#define Mh   64
#define HMx  512

// Scratch (allocation-free rule: __device__ globals)
__device__ float g_q[(size_t)Bx * Sx * HMx];
__device__ float g_k[(size_t)Bx * Sx * HMx];
__device__ float g_v[(size_t)Bx * Sx * HMx];
__device__ float g_m[(size_t)Bx * Sx * HMx];

// ---------------------------------------------------------------------------
// fp32 GEMM: C[16384,512] = A @ W + bias (tiles 128x64x16) — unchanged
// ---------------------------------------------------------------------------
__global__ void __launch_bounds__(256) gemm512_kernel(
    const float* __restrict__ A, const float* __restrict__ W,
    const float* __restrict__ bias, float* __restrict__ C)
{
    const int BM = 128, BN = 64, BK = 16;
    __shared__ float As[BK][BM];
    __shared__ float Bs[BK][BN];

    const int n0  = blockIdx.x * BN;
    const int m0  = blockIdx.y * BM;
    const int tid = threadIdx.x;
    const int tm  = tid >> 4;
    const int tn  = tid & 15;

    float acc[8][4];
#pragma unroll
    for (int i = 0; i < 8; i++)
#pragma unroll
        for (int j = 0; j < 4; j++) acc[i][j] = 0.f;

    for (int kb = 0; kb < 512; kb += BK) {
#pragma unroll
        for (int i = 0; i < 2; i++) {
            int idx = tid + i * 256;
            int row = idx >> 2;
            int c4  = idx & 3;
            float4 a = *(const float4*)&A[(size_t)(m0 + row) * 512 + kb + c4 * 4];
            As[c4 * 4 + 0][row] = a.x;
            As[c4 * 4 + 1][row] = a.y;
            As[c4 * 4 + 2][row] = a.z;
            As[c4 * 4 + 3][row] = a.w;
        }
        {
            int row = tid >> 4;
            int c4  = tid & 15;
            *(float4*)&Bs[row][c4 * 4] =
                *(const float4*)&W[(size_t)(kb + row) * 512 + n0 + c4 * 4];
        }
        __syncthreads();

#pragma unroll
        for (int k = 0; k < BK; k++) {
            float4 a0 = *(const float4*)&As[k][tm * 8];
            float4 a1 = *(const float4*)&As[k][tm * 8 + 4];
            float4 bb = *(const float4*)&Bs[k][tn * 4];
            float a[8] = {a0.x, a0.y, a0.z, a0.w, a1.x, a1.y, a1.z, a1.w};
            float b[4] = {bb.x, bb.y, bb.z, bb.w};
#pragma unroll
            for (int i = 0; i < 8; i++)
#pragma unroll
                for (int j = 0; j < 4; j++) acc[i][j] += a[i] * b[j];
        }
        __syncthreads();
    }

    float4 bia = *(const float4*)&bias[n0 + tn * 4];
#pragma unroll
    for (int i = 0; i < 8; i++) {
        float4 o;
        o.x = acc[i][0] + bia.x;
        o.y = acc[i][1] + bia.y;
        o.z = acc[i][2] + bia.z;
        o.w = acc[i][3] + bia.w;
        *(float4*)&C[(size_t)(m0 + tm * 8 + i) * 512 + n0 + tn * 4] = o;
    }
}

// ---------------------------------------------------------------------------
// tf32 tensor-core flash attention, packed-fragment smem + shuffle P-convert.
// Block = (64-query tile, b, h); 4 warps x 16 rows. Key chunks of 64.
// ---------------------------------------------------------------------------
__device__ __forceinline__ uint32_t f2tf(float x) {
    uint32_t r;
    asm("cvt.rna.tf32.f32 %0, %1;" : "=r"(r) : "f"(x));
    return r;
}

__device__ __forceinline__ void mma_tf32(float* c, const uint32_t* a,
                                         uint32_t b0, uint32_t b1) {
    asm volatile(
        "mma.sync.aligned.m16n8k8.row.col.f32.tf32.tf32.f32 "
        "{%0,%1,%2,%3}, {%4,%5,%6,%7}, {%8,%9}, {%0,%1,%2,%3};"
        : "+f"(c[0]), "+f"(c[1]), "+f"(c[2]), "+f"(c[3])
        : "r"(a[0]), "r"(a[1]), "r"(a[2]), "r"(a[3]), "r"(b0), "r"(b1));
}

__global__ void __launch_bounds__(128) attn_tc_kernel(
    const float* __restrict__ qg, const float* __restrict__ kg,
    const float* __restrict__ vg, const float* __restrict__ mask,
    float* __restrict__ msgs)
{
    // Packed fragment layouts: block (d,j) / (kc,j) = 32 lanes x float2.
    __shared__ float Ks[64 * 64];   // 16 KB
    __shared__ float Vs[64 * 64];   // 16 KB

    const int h  = blockIdx.z;
    const int b  = blockIdx.y;
    const int q0 = blockIdx.x * 64;
    const int tid  = threadIdx.x;
    const int w    = tid >> 5;
    const int lane = tid & 31;
    const int qr   = lane >> 2;   // quad row 0..7
    const int qc   = lane & 3;    // quad col 0..3

    // Fill-role indices (128 threads fill a 64x64 tile, 32 elems each)
    const int frow = tid >> 1;            // key/token row 0..63
    const int fcol = (tid & 1) * 32;      // dim col 0 or 32
    // K packed destination components
    const int kj  = frow >> 3;            // key group
    const int kqr = frow & 7;             // key-in-group
    // V packed destination components
    const int vkc   = frow >> 3;          // key group (contraction)
    const int vqc   = frow & 3;           // key quad col
    const int vslot = (frow >> 2) & 1;    // key offset >= 4

    const int rlo = w * 16 + qr;          // this thread's low query row (in tile)
    const int rhi = rlo + 8;

    // ---- Q fragments straight from global (pre-scaled, tf32) ----
    uint32_t qa[8][4];
    {
        const float* qlo = qg + ((size_t)b * Sx + q0 + rlo) * HMx + h * Mh;
        const float* qhi = qlo + 8 * HMx;
#pragma unroll
        for (int d = 0; d < 8; d++) {
            qa[d][0] = f2tf(qlo[d * 8 + qc]     * 0.125f);
            qa[d][1] = f2tf(qhi[d * 8 + qc]     * 0.125f);
            qa[d][2] = f2tf(qlo[d * 8 + qc + 4] * 0.125f);
            qa[d][3] = f2tf(qhi[d * 8 + qc + 4] * 0.125f);
        }
    }

    float o[8][4];
#pragma unroll
    for (int j = 0; j < 8; j++)
#pragma unroll
        for (int u = 0; u < 4; u++) o[j][u] = 0.f;
    float m_lo = -INFINITY, m_hi = -INFINITY;
    float l_lo = 0.f, l_hi = 0.f;

    const size_t mrow_lo = ((size_t)b * Sx + q0 + rlo) * Sx;
    const size_t mrow_hi = ((size_t)b * Sx + q0 + rhi) * Sx;

    const int srcA = (qr << 2) + (qc >> 1);
    const int srcB = srcA + 2;
    const bool esel = (qc & 1);

    for (int t0 = 0; t0 < Sx; t0 += 64) {
        __syncthreads();   // previous chunk's smem reads done
        // ---- K,V chunk -> packed tf32 smem ----
        {
            const float4* ks = (const float4*)(kg +
                ((size_t)b * Sx + t0 + frow) * HMx + h * Mh + fcol);
            const float4* vs = (const float4*)(vg +
                ((size_t)b * Sx + t0 + frow) * HMx + h * Mh + fcol);
#pragma unroll
            for (int i = 0; i < 8; i++) {
                int c0 = fcol + i * 4;
                float4 kv = ks[i];
                {
                    int d    = c0 >> 3;
                    int slot = (c0 & 7) >= 4;
                    float* kd = Ks + (d * 8 + kj) * 64 + kqr * 8 + slot;
                    kd[0] = __uint_as_float(f2tf(kv.x));
                    kd[2] = __uint_as_float(f2tf(kv.y));
                    kd[4] = __uint_as_float(f2tf(kv.z));
                    kd[6] = __uint_as_float(f2tf(kv.w));
                }
                float4 vv = vs[i];
                {
                    int j   = c0 >> 3;
                    int qr0 = c0 & 7;   // 0 or 4
                    float* vd = Vs + (vkc * 8 + j) * 64 + (qr0 * 4 + vqc) * 2 + vslot;
                    vd[0]  = __uint_as_float(f2tf(vv.x));
                    vd[8]  = __uint_as_float(f2tf(vv.y));
                    vd[16] = __uint_as_float(f2tf(vv.z));
                    vd[24] = __uint_as_float(f2tf(vv.w));
                }
            }
        }
        __syncthreads();

        // ---- S = Q K^T (16x64 per warp); one LDS.64 per mma ----
        float s[8][4];
#pragma unroll
        for (int j = 0; j < 8; j++)
#pragma unroll
            for (int u = 0; u < 4; u++) s[j][u] = 0.f;
#pragma unroll
        for (int d = 0; d < 8; d++) {
#pragma unroll
            for (int j = 0; j < 8; j++) {
                float2 kb = *(const float2*)&Ks[(d * 8 + j) * 64 + lane * 2];
                mma_tf32(s[j], qa[d],
                         __float_as_uint(kb.x), __float_as_uint(kb.y));
            }
        }

        // ---- mask + row max ----
        float rmax_lo = -INFINITY, rmax_hi = -INFINITY;
#pragma unroll
        for (int j = 0; j < 8; j++) {
            int col = t0 + j * 8 + 2 * qc;
            float2 ml = *(const float2*)(mask + mrow_lo + col);
            float2 mh = *(const float2*)(mask + mrow_hi + col);
            s[j][0] = (ml.x > 0.5f) ? s[j][0] : -INFINITY;
            s[j][1] = (ml.y > 0.5f) ? s[j][1] : -INFINITY;
            s[j][2] = (mh.x > 0.5f) ? s[j][2] : -INFINITY;
            s[j][3] = (mh.y > 0.5f) ? s[j][3] : -INFINITY;
            rmax_lo = fmaxf(rmax_lo, fmaxf(s[j][0], s[j][1]));
            rmax_hi = fmaxf(rmax_hi, fmaxf(s[j][2], s[j][3]));
        }
        rmax_lo = fmaxf(rmax_lo, __shfl_xor_sync(0xffffffff, rmax_lo, 1));
        rmax_lo = fmaxf(rmax_lo, __shfl_xor_sync(0xffffffff, rmax_lo, 2));
        rmax_hi = fmaxf(rmax_hi, __shfl_xor_sync(0xffffffff, rmax_hi, 1));
        rmax_hi = fmaxf(rmax_hi, __shfl_xor_sync(0xffffffff, rmax_hi, 2));

        float mn_lo = fmaxf(m_lo, rmax_lo);
        float mn_hi = fmaxf(m_hi, rmax_hi);
        float safe_lo = (mn_lo > -INFINITY) ? mn_lo : 0.f;
        float safe_hi = (mn_hi > -INFINITY) ? mn_hi : 0.f;
        float al = __expf(m_lo - safe_lo);   // -inf -> 0
        float ah = __expf(m_hi - safe_hi);

        // ---- P = exp(S - m), row sums ----
        float rs_lo = 0.f, rs_hi = 0.f;
#pragma unroll
        for (int j = 0; j < 8; j++) {
            s[j][0] = __expf(s[j][0] - safe_lo);
            s[j][1] = __expf(s[j][1] - safe_lo);
            s[j][2] = __expf(s[j][2] - safe_hi);
            s[j][3] = __expf(s[j][3] - safe_hi);
            rs_lo += s[j][0] + s[j][1];
            rs_hi += s[j][2] + s[j][3];
        }
        rs_lo += __shfl_xor_sync(0xffffffff, rs_lo, 1);
        rs_lo += __shfl_xor_sync(0xffffffff, rs_lo, 2);
        rs_hi += __shfl_xor_sync(0xffffffff, rs_hi, 1);
        rs_hi += __shfl_xor_sync(0xffffffff, rs_hi, 2);

        l_lo = l_lo * al + rs_lo;
        l_hi = l_hi * ah + rs_hi;
        m_lo = mn_lo;
        m_hi = mn_hi;

        // ---- rescale O ----
#pragma unroll
        for (int j = 0; j < 8; j++) {
            o[j][0] *= al; o[j][1] *= al;
            o[j][2] *= ah; o[j][3] *= ah;
        }

        // ---- O += P V : quad-shuffle C-frag -> A-frag, then mma ----
#pragma unroll
        for (int kc = 0; kc < 8; kc++) {
            float t0v = __shfl_sync(0xffffffffu, s[kc][0], srcA);
            float t1v = __shfl_sync(0xffffffffu, s[kc][1], srcA);
            float t2v = __shfl_sync(0xffffffffu, s[kc][2], srcA);
            float t3v = __shfl_sync(0xffffffffu, s[kc][3], srcA);
            float u0v = __shfl_sync(0xffffffffu, s[kc][0], srcB);
            float u1v = __shfl_sync(0xffffffffu, s[kc][1], srcB);
            float u2v = __shfl_sync(0xffffffffu, s[kc][2], srcB);
            float u3v = __shfl_sync(0xffffffffu, s[kc][3], srcB);
            uint32_t a[4];
            a[0] = f2tf(esel ? t1v : t0v);
            a[1] = f2tf(esel ? t3v : t2v);
            a[2] = f2tf(esel ? u1v : u0v);
            a[3] = f2tf(esel ? u3v : u2v);
#pragma unroll
            for (int j = 0; j < 8; j++) {
                float2 vb = *(const float2*)&Vs[(kc * 8 + j) * 64 + lane * 2];
                mma_tf32(o[j], a,
                         __float_as_uint(vb.x), __float_as_uint(vb.y));
            }
        }
    }

    // ---- epilogue: normalize; fully-masked rows -> 0 ----
    float il_lo = (l_lo > 0.f) ? (1.0f / l_lo) : 0.f;
    float il_hi = (l_hi > 0.f) ? (1.0f / l_hi) : 0.f;
    float* out_lo = msgs + ((size_t)b * Sx + q0 + rlo) * HMx + h * Mh;
    float* out_hi = msgs + ((size_t)b * Sx + q0 + rhi) * HMx + h * Mh;
#pragma unroll
    for (int j = 0; j < 8; j++) {
        float2 vlo, vhi;
        vlo.x = o[j][0] * il_lo; vlo.y = o[j][1] * il_lo;
        vhi.x = o[j][2] * il_hi; vhi.y = o[j][3] * il_hi;
        *(float2*)(out_lo + j * 8 + 2 * qc) = vlo;
        *(float2*)(out_hi + j * 8 + 2 * qc) = vhi;
    }
}

// ---------------------------------------------------------------------------
extern "C" void kernel_launch(void* const* d_in, const int* in_sizes, int n_in,
                              void* d_out, int out_size)
{
    (void)in_sizes; (void)n_in; (void)out_size;
    const float* x    = (const float*)d_in[0];
    const float* mask = (const float*)d_in[1];
    const float* Wq   = (const float*)d_in[2];
    const float* Wk   = (const float*)d_in[3];
    const float* Wv   = (const float*)d_in[4];
    const float* bq   = (const float*)d_in[5];
    const float* bk   = (const float*)d_in[6];
    const float* bv   = (const float*)d_in[7];
    const float* Wo   = (const float*)d_in[8];
    const float* bo   = (const float*)d_in[9];
    float* out = (float*)d_out;

    float *qp, *kp, *vp, *mp;
    cudaGetSymbolAddress((void**)&qp, g_q);
    cudaGetSymbolAddress((void**)&kp, g_k);
    cudaGetSymbolAddress((void**)&vp, g_v);
    cudaGetSymbolAddress((void**)&mp, g_m);

    dim3 gg(512 / 64, (Bx * Sx) / 128);
    gemm512_kernel<<<gg, 256>>>(x, Wq, bq, qp);
    gemm512_kernel<<<gg, 256>>>(x, Wk, bk, kp);
    gemm512_kernel<<<gg, 256>>>(x, Wv, bv, vp);

    dim3 ga(Sx / 64, Bx, Hx);   // (32, 8, 8)
    attn_tc_kernel<<<ga, 128>>>(qp, kp, vp, mask, mp);

    gemm512_kernel<<<gg, 256>>>(mp, Wo, bo, out);
}

// round 4
// speedup vs baseline: 2.1372x; 1.1236x over previous
#include <cuda_runtime.h>
#include <math.h>
#include <stdint.h>

#define Bx   8
#define Sx   2048
#define Hx   8
#define Mh   64
#define HMx  512

// ---------------------------------------------------------------------------
// Global scratch (allocation-free rule)
// ---------------------------------------------------------------------------
__device__ float g_xp[(size_t)Bx * Sx * HMx];   // x  in A-frag pack (tf32)
__device__ float g_q [(size_t)Bx * Sx * HMx];   // Q  in A-frag pack (tf32, +bias)
__device__ float g_k [(size_t)Bx * Sx * HMx];   // K  in B-frag pack (tf32, +bias)
__device__ float g_v [(size_t)Bx * Sx * HMx];   // V  in B-frag pack (tf32, +bias)
__device__ float g_m [(size_t)Bx * Sx * HMx];   // msgs in A-frag pack (tf32)
__device__ float g_wq[512 * 512];
__device__ float g_wk[512 * 512];
__device__ float g_wv[512 * 512];
__device__ float g_wo[512 * 512];

__device__ __forceinline__ uint32_t f2tf(float x) {
    uint32_t r;
    asm("cvt.rna.tf32.f32 %0, %1;" : "=r"(r) : "f"(x));
    return r;
}
__device__ __forceinline__ void mma_tf32(float* c, const uint32_t* a,
                                         uint32_t b0, uint32_t b1) {
    asm volatile(
        "mma.sync.aligned.m16n8k8.row.col.f32.tf32.tf32.f32 "
        "{%0,%1,%2,%3}, {%4,%5,%6,%7}, {%8,%9}, {%0,%1,%2,%3};"
        : "+f"(c[0]), "+f"(c[1]), "+f"(c[2]), "+f"(c[3])
        : "r"(a[0]), "r"(a[1]), "r"(a[2]), "r"(a[3]), "r"(b0), "r"(b1));
}

// Layouts:
// A-pack:  [((mb*64 + dg)*32 + lane)*4 + idx]
//    e: idx = (row%16>=8) + 2*((col%8)>=4); lane = (row%8)*4 + (col%8)%4
// W-pack:  [((dg*64 + jg)*32 + lane)*2 + s]   dg=k/8, jg=n/8
//    lane = (n%8)*4 + (k%8)%4 ; s = (k%8)/4
// K-pack:  [(((bh*8 + d)*256 + jt)*32 + lane)*2 + s]  (bh = b*8+h)
//    lane = (tok%8)*4 + (dim%8)%4 ; s = (dim%8)/4 ; jt = tok/8, d = dim/8
// V-pack:  [(((bh*256 + kc)*8 + j)*32 + lane)*2 + s]
//    lane = (dim%8)*4 + (tok%4) ; s = (tok%8)/4 ; kc = tok/8, j = dim/8

// ---------------------------------------------------------------------------
// prep: x[16384,512] -> A-pack tf32
// ---------------------------------------------------------------------------
__global__ void prep_x_kernel(const float* __restrict__ x, float* __restrict__ xp)
{
    int t  = blockIdx.x * 256 + threadIdx.x;   // 16384*128 threads
    int r  = t >> 7;
    int c4 = (t & 127) << 2;
    float4 v = *(const float4*)&x[(size_t)r * 512 + c4];
    int mb = r >> 4, rr = r & 15;
    int qrp = rr & 7, hi = rr >> 3;
    float vv[4] = {v.x, v.y, v.z, v.w};
#pragma unroll
    for (int i = 0; i < 4; i++) {
        int col = c4 + i;
        int dg = col >> 3, cc = col & 7;
        int lane = qrp * 4 + (cc & 3);
        int idx  = hi + ((cc >> 2) << 1);
        xp[(size_t)(mb * 64 + dg) * 128 + lane * 4 + idx] =
            __uint_as_float(f2tf(vv[i]));
    }
}

// ---------------------------------------------------------------------------
// prep: W[512,512] -> W-pack tf32
// ---------------------------------------------------------------------------
__global__ void prep_w_kernel(const float* __restrict__ Wsrc, float* __restrict__ wp)
{
    int t  = blockIdx.x * 256 + threadIdx.x;   // 512*128 threads
    int k  = t >> 7;
    int c4 = (t & 127) << 2;
    float4 v = *(const float4*)&Wsrc[(size_t)k * 512 + c4];
    int dg = k >> 3, kk = k & 7;
    int s  = kk >> 2;
    float vv[4] = {v.x, v.y, v.z, v.w};
#pragma unroll
    for (int i = 0; i < 4; i++) {
        int n = c4 + i;
        int jg = n >> 3, nn = n & 7;
        int lane = nn * 4 + (kk & 3);
        wp[(size_t)(dg * 64 + jg) * 64 + lane * 2 + s] =
            __uint_as_float(f2tf(vv[i]));
    }
}

// ---------------------------------------------------------------------------
// tf32 GEMM, smem-free: C[16384,512] = A @ W + bias.
// grid (8, 256), 128 thr; warp = 16 rows x 64 cols.
// MODE: 0 = plain fp32, 1 = K-pack, 2 = V-pack, 3 = A-pack
// ---------------------------------------------------------------------------
template<int MODE>
__global__ void __launch_bounds__(128) gemm_tc_kernel(
    const float* __restrict__ Ap, const float* __restrict__ Wp,
    const float* __restrict__ bias, float* __restrict__ out)
{
    const int w    = threadIdx.x >> 5;
    const int lane = threadIdx.x & 31;
    const int qr   = lane >> 2;
    const int qc   = lane & 3;
    const int nb   = blockIdx.x;              // n-block (64 cols) == head for K/V
    const int mb   = blockIdx.y * 4 + w;      // 16-row group

    float o[8][4];
#pragma unroll
    for (int j = 0; j < 8; j++)
#pragma unroll
        for (int u = 0; u < 4; u++) o[j][u] = 0.f;

    const float* abase = Ap + (size_t)mb * 8192 + lane * 4;
    const float* wbase = Wp + (size_t)nb * 512 + lane * 2;   // + dg*4096 + jc*64

    for (int ck = 0; ck < 8; ck++) {
        uint32_t qa[8][4];
#pragma unroll
        for (int dd = 0; dd < 8; dd++) {
            float4 a4 = *(const float4*)(abase + (ck * 8 + dd) * 128);
            qa[dd][0] = __float_as_uint(a4.x);
            qa[dd][1] = __float_as_uint(a4.y);
            qa[dd][2] = __float_as_uint(a4.z);
            qa[dd][3] = __float_as_uint(a4.w);
        }
#pragma unroll
        for (int dd = 0; dd < 8; dd++) {
#pragma unroll
            for (int jc = 0; jc < 8; jc++) {
                float2 wb = *(const float2*)(wbase + (size_t)(ck * 8 + dd) * 4096 + jc * 64);
                mma_tf32(o[jc], qa[dd],
                         __float_as_uint(wb.x), __float_as_uint(wb.y));
            }
        }
    }

    const int rlo = mb * 16 + qr;
    const int rhi = rlo + 8;
    const int n0  = nb * 64;

    if (MODE == 0) {
#pragma unroll
        for (int jc = 0; jc < 8; jc++) {
            int col = n0 + jc * 8 + 2 * qc;
            float2 bb = *(const float2*)&bias[col];
            float2 lo_v = {o[jc][0] + bb.x, o[jc][1] + bb.y};
            float2 hi_v = {o[jc][2] + bb.x, o[jc][3] + bb.y};
            *(float2*)&out[(size_t)rlo * 512 + col] = lo_v;
            *(float2*)&out[(size_t)rhi * 512 + col] = hi_v;
        }
    } else if (MODE == 3) {
        // A-pack epilogue (rows of this warp all share mb)
#pragma unroll
        for (int jc = 0; jc < 8; jc++) {
            int dg = nb * 8 + jc;
            float2 bb = *(const float2*)&bias[n0 + jc * 8 + 2 * qc];
            float* base = out + (size_t)(mb * 64 + dg) * 128;
#pragma unroll
            for (int e = 0; e < 2; e++) {
                int cc = 2 * qc + e;
                int la = qr * 4 + (cc & 3);
                int ix = (cc >> 2) << 1;
                float bv = e ? bb.y : bb.x;
                base[la * 4 + ix]     = __uint_as_float(f2tf(o[jc][e]     + bv));
                base[la * 4 + ix + 1] = __uint_as_float(f2tf(o[jc][e + 2] + bv));
            }
        }
    } else if (MODE == 1) {
        // K-pack: tok = row (within b), dim = col - h*64
        int b   = rlo >> 11;
        int tok = rlo & 2047;            // rhi same b (row blocks of 64 within 2048)
        int jt_lo = tok >> 3;            // rhi -> jt_lo + 1
        int qrk = tok & 7;               // same for rhi
        float* base = out + ((size_t)(b * 8 + nb) * 8) * 16384;
#pragma unroll
        for (int jc = 0; jc < 8; jc++) {
            float2 bb = *(const float2*)&bias[n0 + jc * 8 + 2 * qc];
            float* dbase = base + (size_t)jc * 16384;
#pragma unroll
            for (int e = 0; e < 2; e++) {
                int cc = 2 * qc + e;
                int lk = qrk * 4 + (cc & 3);
                int s  = cc >> 2;
                float bv = e ? bb.y : bb.x;
                dbase[(size_t)jt_lo * 64 + lk * 2 + s]       = __uint_as_float(f2tf(o[jc][e]     + bv));
                dbase[(size_t)(jt_lo + 1) * 64 + lk * 2 + s] = __uint_as_float(f2tf(o[jc][e + 2] + bv));
            }
        }
    } else {
        // V-pack
        int b   = rlo >> 11;
        int tok = rlo & 2047;
        int kc_lo = tok >> 3;            // rhi -> kc_lo + 1
        int s_v   = (tok & 7) >> 2;      // same for rhi (tok%8 = qr for both)
        int t4    = tok & 3;
        float* base = out + ((size_t)(b * 8 + nb) * 256) * 512;
#pragma unroll
        for (int jc = 0; jc < 8; jc++) {
            float2 bb = *(const float2*)&bias[n0 + jc * 8 + 2 * qc];
#pragma unroll
            for (int e = 0; e < 2; e++) {
                int cc = 2 * qc + e;
                int lv = cc * 4 + t4;
                float bv = e ? bb.y : bb.x;
                base[(size_t)kc_lo * 512 + jc * 64 + lv * 2 + s_v] =
                    __uint_as_float(f2tf(o[jc][e] + bv));
                base[(size_t)(kc_lo + 1) * 512 + jc * 64 + lv * 2 + s_v] =
                    __uint_as_float(f2tf(o[jc][e + 2] + bv));
            }
        }
    }
}

// ---------------------------------------------------------------------------
// tf32 flash attention, smem-free: K/V read as packed B-frags from global.
// Block = (64 queries, b, h); 4 warps x 16 rows; key chunks of 64.
// ---------------------------------------------------------------------------
__global__ void __launch_bounds__(128) attn_tc_kernel(
    const float* __restrict__ Qp, const float* __restrict__ Kp,
    const float* __restrict__ Vp, const float* __restrict__ mask,
    float* __restrict__ Mp)
{
    const int h  = blockIdx.z;
    const int b  = blockIdx.y;
    const int q0 = blockIdx.x * 64;
    const int tid  = threadIdx.x;
    const int w    = tid >> 5;
    const int lane = tid & 31;
    const int qr   = lane >> 2;
    const int qc   = lane & 3;

    const int mbq = b * 128 + (q0 >> 4) + w;   // 16-row group of this warp

    // ---- Q fragments: 8 x LDG.128 from A-pack, scale by rsqrt(64) ----
    uint32_t qa[8][4];
    {
        const float* qb = Qp + (size_t)mbq * 8192 + h * 1024 + lane * 4;
#pragma unroll
        for (int dd = 0; dd < 8; dd++) {
            float4 a4 = *(const float4*)(qb + dd * 128);
            qa[dd][0] = __float_as_uint(a4.x * 0.125f);
            qa[dd][1] = __float_as_uint(a4.y * 0.125f);
            qa[dd][2] = __float_as_uint(a4.z * 0.125f);
            qa[dd][3] = __float_as_uint(a4.w * 0.125f);
        }
    }

    float o[8][4];
#pragma unroll
    for (int j = 0; j < 8; j++)
#pragma unroll
        for (int u = 0; u < 4; u++) o[j][u] = 0.f;
    float m_lo = -INFINITY, m_hi = -INFINITY;
    float l_lo = 0.f, l_hi = 0.f;

    const int rlo = w * 16 + qr;
    const int rhi = rlo + 8;
    const size_t mrow_lo = ((size_t)b * Sx + q0 + rlo) * Sx;
    const size_t mrow_hi = ((size_t)b * Sx + q0 + rhi) * Sx;

    const size_t bh = (size_t)(b * 8 + h);
    const float* kbase = Kp + bh * 131072 + lane * 2;   // + dd*16384 + jt*64
    const float* vbase = Vp + bh * 131072 + lane * 2;   // + kc*512 + j*64

    const int srcA = (qr << 2) + (qc >> 1);
    const int srcB = srcA + 2;
    const bool esel = (qc & 1);

    for (int t0 = 0; t0 < Sx; t0 += 64) {
        const int jt0 = t0 >> 3;

        // ---- S = Q K^T ----
        float s[8][4];
#pragma unroll
        for (int j = 0; j < 8; j++)
#pragma unroll
            for (int u = 0; u < 4; u++) s[j][u] = 0.f;
#pragma unroll
        for (int dd = 0; dd < 8; dd++) {
            const float* kd = kbase + dd * 16384 + (size_t)jt0 * 64;
#pragma unroll
            for (int j = 0; j < 8; j++) {
                float2 kb = *(const float2*)(kd + j * 64);
                mma_tf32(s[j], qa[dd],
                         __float_as_uint(kb.x), __float_as_uint(kb.y));
            }
        }

        // ---- mask + row max ----
        float rmax_lo = -INFINITY, rmax_hi = -INFINITY;
#pragma unroll
        for (int j = 0; j < 8; j++) {
            int col = t0 + j * 8 + 2 * qc;
            float2 ml = *(const float2*)(mask + mrow_lo + col);
            float2 mh = *(const float2*)(mask + mrow_hi + col);
            s[j][0] = (ml.x > 0.5f) ? s[j][0] : -INFINITY;
            s[j][1] = (ml.y > 0.5f) ? s[j][1] : -INFINITY;
            s[j][2] = (mh.x > 0.5f) ? s[j][2] : -INFINITY;
            s[j][3] = (mh.y > 0.5f) ? s[j][3] : -INFINITY;
            rmax_lo = fmaxf(rmax_lo, fmaxf(s[j][0], s[j][1]));
            rmax_hi = fmaxf(rmax_hi, fmaxf(s[j][2], s[j][3]));
        }
        rmax_lo = fmaxf(rmax_lo, __shfl_xor_sync(0xffffffff, rmax_lo, 1));
        rmax_lo = fmaxf(rmax_lo, __shfl_xor_sync(0xffffffff, rmax_lo, 2));
        rmax_hi = fmaxf(rmax_hi, __shfl_xor_sync(0xffffffff, rmax_hi, 1));
        rmax_hi = fmaxf(rmax_hi, __shfl_xor_sync(0xffffffff, rmax_hi, 2));

        float mn_lo = fmaxf(m_lo, rmax_lo);
        float mn_hi = fmaxf(m_hi, rmax_hi);
        float safe_lo = (mn_lo > -INFINITY) ? mn_lo : 0.f;
        float safe_hi = (mn_hi > -INFINITY) ? mn_hi : 0.f;
        float al = __expf(m_lo - safe_lo);
        float ah = __expf(m_hi - safe_hi);

        float rs_lo = 0.f, rs_hi = 0.f;
#pragma unroll
        for (int j = 0; j < 8; j++) {
            s[j][0] = __expf(s[j][0] - safe_lo);
            s[j][1] = __expf(s[j][1] - safe_lo);
            s[j][2] = __expf(s[j][2] - safe_hi);
            s[j][3] = __expf(s[j][3] - safe_hi);
            rs_lo += s[j][0] + s[j][1];
            rs_hi += s[j][2] + s[j][3];
        }
        rs_lo += __shfl_xor_sync(0xffffffff, rs_lo, 1);
        rs_lo += __shfl_xor_sync(0xffffffff, rs_lo, 2);
        rs_hi += __shfl_xor_sync(0xffffffff, rs_hi, 1);
        rs_hi += __shfl_xor_sync(0xffffffff, rs_hi, 2);

        l_lo = l_lo * al + rs_lo;
        l_hi = l_hi * ah + rs_hi;
        m_lo = mn_lo;
        m_hi = mn_hi;

#pragma unroll
        for (int j = 0; j < 8; j++) {
            o[j][0] *= al; o[j][1] *= al;
            o[j][2] *= ah; o[j][3] *= ah;
        }

        // ---- O += P V (shuffle C-frag -> A-frag) ----
#pragma unroll
        for (int kc = 0; kc < 8; kc++) {
            float t0v = __shfl_sync(0xffffffffu, s[kc][0], srcA);
            float t1v = __shfl_sync(0xffffffffu, s[kc][1], srcA);
            float t2v = __shfl_sync(0xffffffffu, s[kc][2], srcA);
            float t3v = __shfl_sync(0xffffffffu, s[kc][3], srcA);
            float u0v = __shfl_sync(0xffffffffu, s[kc][0], srcB);
            float u1v = __shfl_sync(0xffffffffu, s[kc][1], srcB);
            float u2v = __shfl_sync(0xffffffffu, s[kc][2], srcB);
            float u3v = __shfl_sync(0xffffffffu, s[kc][3], srcB);
            uint32_t a[4];
            a[0] = f2tf(esel ? t1v : t0v);
            a[1] = f2tf(esel ? t3v : t2v);
            a[2] = f2tf(esel ? u1v : u0v);
            a[3] = f2tf(esel ? u3v : u2v);
            const float* vd = vbase + (size_t)(jt0 + kc) * 512;
#pragma unroll
            for (int j = 0; j < 8; j++) {
                float2 vb = *(const float2*)(vd + j * 64);
                mma_tf32(o[j], a,
                         __float_as_uint(vb.x), __float_as_uint(vb.y));
            }
        }
    }

    // ---- epilogue: normalize, write msgs in A-pack tf32 ----
    float il_lo = (l_lo > 0.f) ? (1.0f / l_lo) : 0.f;
    float il_hi = (l_hi > 0.f) ? (1.0f / l_hi) : 0.f;
#pragma unroll
    for (int jc = 0; jc < 8; jc++) {
        float* base = Mp + (size_t)(mbq * 64 + h * 8 + jc) * 128;
#pragma unroll
        for (int e = 0; e < 2; e++) {
            int cc = 2 * qc + e;
            int la = qr * 4 + (cc & 3);
            int ix = (cc >> 2) << 1;
            base[la * 4 + ix]     = __uint_as_float(f2tf(o[jc][e]     * il_lo));
            base[la * 4 + ix + 1] = __uint_as_float(f2tf(o[jc][e + 2] * il_hi));
        }
    }
}

// ---------------------------------------------------------------------------
extern "C" void kernel_launch(void* const* d_in, const int* in_sizes, int n_in,
                              void* d_out, int out_size)
{
    (void)in_sizes; (void)n_in; (void)out_size;
    const float* x    = (const float*)d_in[0];
    const float* mask = (const float*)d_in[1];
    const float* Wq   = (const float*)d_in[2];
    const float* Wk   = (const float*)d_in[3];
    const float* Wv   = (const float*)d_in[4];
    const float* bq   = (const float*)d_in[5];
    const float* bk   = (const float*)d_in[6];
    const float* bv   = (const float*)d_in[7];
    const float* Wo   = (const float*)d_in[8];
    const float* bo   = (const float*)d_in[9];
    float* out = (float*)d_out;

    float *xp, *qp, *kp, *vp, *mp, *wqp, *wkp, *wvp, *wop;
    cudaGetSymbolAddress((void**)&xp,  g_xp);
    cudaGetSymbolAddress((void**)&qp,  g_q);
    cudaGetSymbolAddress((void**)&kp,  g_k);
    cudaGetSymbolAddress((void**)&vp,  g_v);
    cudaGetSymbolAddress((void**)&mp,  g_m);
    cudaGetSymbolAddress((void**)&wqp, g_wq);
    cudaGetSymbolAddress((void**)&wkp, g_wk);
    cudaGetSymbolAddress((void**)&wvp, g_wv);
    cudaGetSymbolAddress((void**)&wop, g_wo);

    prep_x_kernel<<<8192, 256>>>(x, xp);
    prep_w_kernel<<<256, 256>>>(Wq, wqp);
    prep_w_kernel<<<256, 256>>>(Wk, wkp);
    prep_w_kernel<<<256, 256>>>(Wv, wvp);
    prep_w_kernel<<<256, 256>>>(Wo, wop);

    dim3 gg(8, 256);
    gemm_tc_kernel<3><<<gg, 128>>>(xp, wqp, bq, qp);   // Q -> A-pack
    gemm_tc_kernel<1><<<gg, 128>>>(xp, wkp, bk, kp);   // K -> B-frag pack
    gemm_tc_kernel<2><<<gg, 128>>>(xp, wvp, bv, vp);   // V -> B-frag pack

    dim3 ga(Sx / 64, Bx, Hx);   // (32, 8, 8)
    attn_tc_kernel<<<ga, 128>>>(qp, kp, vp, mask, mp);

    gemm_tc_kernel<0><<<gg, 128>>>(mp, wop, bo, out);  // final projection
}

// round 5
// speedup vs baseline: 2.7636x; 1.2931x over previous
#include <cuda_runtime.h>
#include <math.h>
#include <stdint.h>

#define Bx   8
#define Sx   2048
#define Hx   8
#define Mh   64
#define HMx  512

// ---------------------------------------------------------------------------
// Global scratch (allocation-free rule)
// ---------------------------------------------------------------------------
__device__ float g_xp[(size_t)Bx * Sx * HMx];   // x  in A-frag pack (tf32)
__device__ float g_q [(size_t)Bx * Sx * HMx];   // Q  in A-frag pack (tf32, +bias)
__device__ float g_k [(size_t)Bx * Sx * HMx];   // K  in paired B-frag pack
__device__ float g_v [(size_t)Bx * Sx * HMx];   // V  in paired B-frag pack
__device__ float g_m [(size_t)Bx * Sx * HMx];   // msgs in A-frag pack (tf32)
__device__ float g_wq[512 * 512];
__device__ float g_wk[512 * 512];
__device__ float g_wv[512 * 512];
__device__ float g_wo[512 * 512];
__device__ unsigned long long g_mb[(size_t)Bx * Sx * 32];  // mask bitwords

__device__ __forceinline__ uint32_t f2tf(float x) {
    uint32_t r;
    asm("cvt.rna.tf32.f32 %0, %1;" : "=r"(r) : "f"(x));
    return r;
}
__device__ __forceinline__ void mma_tf32(float* c, const uint32_t* a,
                                         uint32_t b0, uint32_t b1) {
    asm volatile(
        "mma.sync.aligned.m16n8k8.row.col.f32.tf32.tf32.f32 "
        "{%0,%1,%2,%3}, {%4,%5,%6,%7}, {%8,%9}, {%0,%1,%2,%3};"
        : "+f"(c[0]), "+f"(c[1]), "+f"(c[2]), "+f"(c[3])
        : "r"(a[0]), "r"(a[1]), "r"(a[2]), "r"(a[3]), "r"(b0), "r"(b1));
}

// Layouts (all tf32 bit patterns stored as float):
// A-pack:  off = mb*8192 + dg*128 + lane*4 + idx
//          lane=(row%8)*4+(col%8)%4 ; idx=(row%16>=8) + 2*((col%8)>=4)
// W-pack (paired jg): off = dg*4096 + jp*128 + lane*4 + jo*2 + s
//          dg=k/8, jp=(n/8)>>1, jo=(n/8)&1, lane=(n%8)*4+(k%8)%4, s=(k%8)/4
// K-pack (paired jt): off(bh) = d*16384 + jtp*128 + lane*4 + jto*2 + s
//          d=dim/8, jt=tok/8, jtp=jt>>1, jto=jt&1,
//          lane=(tok%8)*4+(dim%8)%4, s=(dim%8)/4
// V-pack (paired j):  off(bh) = kc*512 + jp*128 + lane*4 + jo*2 + s
//          kc=tok/8, j=dim/8, jp=j>>1, jo=j&1,
//          lane=(dim%8)*4+(tok%4), s=(tok%8)/4

// ---------------------------------------------------------------------------
// prep: x[16384,512] -> A-pack tf32
// ---------------------------------------------------------------------------
__global__ void prep_x_kernel(const float* __restrict__ x, float* __restrict__ xp)
{
    int t  = blockIdx.x * 256 + threadIdx.x;
    int r  = t >> 7;
    int c4 = (t & 127) << 2;
    float4 v = *(const float4*)&x[(size_t)r * 512 + c4];
    int mb = r >> 4, rr = r & 15;
    int qrp = rr & 7, hi = rr >> 3;
    float vv[4] = {v.x, v.y, v.z, v.w};
#pragma unroll
    for (int i = 0; i < 4; i++) {
        int col = c4 + i;
        int dg = col >> 3, cc = col & 7;
        int lane = qrp * 4 + (cc & 3);
        int idx  = hi + ((cc >> 2) << 1);
        xp[(size_t)(mb * 64 + dg) * 128 + lane * 4 + idx] =
            __uint_as_float(f2tf(vv[i]));
    }
}

// ---------------------------------------------------------------------------
// prep: W[512,512] -> paired W-pack tf32
// ---------------------------------------------------------------------------
__global__ void prep_w_kernel(const float* __restrict__ Wsrc, float* __restrict__ wp)
{
    int t  = blockIdx.x * 256 + threadIdx.x;
    int k  = t >> 7;
    int c4 = (t & 127) << 2;
    float4 v = *(const float4*)&Wsrc[(size_t)k * 512 + c4];
    int dg = k >> 3, kk = k & 7;
    int s  = kk >> 2;
    float vv[4] = {v.x, v.y, v.z, v.w};
#pragma unroll
    for (int i = 0; i < 4; i++) {
        int n = c4 + i;
        int jg = n >> 3, nn = n & 7;
        int lane = nn * 4 + (kk & 3);
        wp[(size_t)dg * 4096 + (jg >> 1) * 128 + lane * 4 + (jg & 1) * 2 + s] =
            __uint_as_float(f2tf(vv[i]));
    }
}

// ---------------------------------------------------------------------------
// prep: mask[B,S,S] float -> 64-bit words (bit i of word w = mask col w*64+i)
// ---------------------------------------------------------------------------
__global__ void prep_mask_kernel(const float* __restrict__ mask,
                                 unsigned long long* __restrict__ mb)
{
    int warp = blockIdx.x * 8 + (threadIdx.x >> 5);   // row id 0..16383
    int lane = threadIdx.x & 31;
    const float* row = mask + (size_t)warp * 2048;
    unsigned long long* dst = mb + (size_t)warp * 32;
#pragma unroll 4
    for (int w = 0; w < 32; w++) {
        float m0 = row[w * 64 + lane];
        float m1 = row[w * 64 + 32 + lane];
        unsigned b0 = __ballot_sync(0xffffffffu, m0 > 0.5f);
        unsigned b1 = __ballot_sync(0xffffffffu, m1 > 0.5f);
        if (lane == 0)
            dst[w] = ((unsigned long long)b1 << 32) | b0;
    }
}

// ---------------------------------------------------------------------------
// tf32 GEMM, smem-free, paired W loads. grid (8, 256), 128 thr.
// MODE: 0 = plain fp32 out, 1 = K-pack, 2 = V-pack, 3 = A-pack
// ---------------------------------------------------------------------------
template<int MODE>
__global__ void __launch_bounds__(128) gemm_tc_kernel(
    const float* __restrict__ Ap, const float* __restrict__ Wp,
    const float* __restrict__ bias, float* __restrict__ out)
{
    const int w    = threadIdx.x >> 5;
    const int lane = threadIdx.x & 31;
    const int qr   = lane >> 2;
    const int qc   = lane & 3;
    const int nb   = blockIdx.x;              // 64-col block == head for K/V
    const int mb   = blockIdx.y * 4 + w;      // 16-row group

    float o[8][4];
#pragma unroll
    for (int j = 0; j < 8; j++)
#pragma unroll
        for (int u = 0; u < 4; u++) o[j][u] = 0.f;

    const float* abase = Ap + (size_t)mb * 8192 + lane * 4;
    const float* wbase = Wp + (size_t)nb * 512 + lane * 4;

    for (int ck = 0; ck < 8; ck++) {
        uint32_t qa[8][4];
#pragma unroll
        for (int dd = 0; dd < 8; dd++) {
            float4 a4 = *(const float4*)(abase + (ck * 8 + dd) * 128);
            qa[dd][0] = __float_as_uint(a4.x);
            qa[dd][1] = __float_as_uint(a4.y);
            qa[dd][2] = __float_as_uint(a4.z);
            qa[dd][3] = __float_as_uint(a4.w);
        }
#pragma unroll
        for (int dd = 0; dd < 8; dd++) {
            const float* wd = wbase + (size_t)(ck * 8 + dd) * 4096;
#pragma unroll
            for (int jp = 0; jp < 4; jp++) {
                float4 wv = *(const float4*)(wd + jp * 128);
                mma_tf32(o[jp * 2],     qa[dd],
                         __float_as_uint(wv.x), __float_as_uint(wv.y));
                mma_tf32(o[jp * 2 + 1], qa[dd],
                         __float_as_uint(wv.z), __float_as_uint(wv.w));
            }
        }
    }

    const int rlo = mb * 16 + qr;
    const int n0  = nb * 64;

    if (MODE == 0) {
        const int rhi = rlo + 8;
#pragma unroll
        for (int jc = 0; jc < 8; jc++) {
            int col = n0 + jc * 8 + 2 * qc;
            float2 bb = *(const float2*)&bias[col];
            float2 lo_v = {o[jc][0] + bb.x, o[jc][1] + bb.y};
            float2 hi_v = {o[jc][2] + bb.x, o[jc][3] + bb.y};
            *(float2*)&out[(size_t)rlo * 512 + col] = lo_v;
            *(float2*)&out[(size_t)rhi * 512 + col] = hi_v;
        }
    } else if (MODE == 3) {
        // A-pack epilogue
#pragma unroll
        for (int jc = 0; jc < 8; jc++) {
            int dg = nb * 8 + jc;
            float2 bb = *(const float2*)&bias[n0 + jc * 8 + 2 * qc];
            float* base = out + (size_t)(mb * 64 + dg) * 128;
#pragma unroll
            for (int e = 0; e < 2; e++) {
                int cc = 2 * qc + e;
                int la = qr * 4 + (cc & 3);
                int ix = (cc >> 2) << 1;
                float bv = e ? bb.y : bb.x;
                base[la * 4 + ix]     = __uint_as_float(f2tf(o[jc][e]     + bv));
                base[la * 4 + ix + 1] = __uint_as_float(f2tf(o[jc][e + 2] + bv));
            }
        }
    } else if (MODE == 1) {
        // K-pack (paired jt): rlo -> jto=0, rhi -> jto=1, same jtp
        int b   = rlo >> 11;
        int tok = rlo & 2047;
        int jtp = tok >> 4;
        int qrk = tok & 7;
        float* base = out + (size_t)(b * 8 + nb) * 131072;
#pragma unroll
        for (int jc = 0; jc < 8; jc++) {
            float2 bb = *(const float2*)&bias[n0 + jc * 8 + 2 * qc];
            float* dbase = base + (size_t)jc * 16384 + jtp * 128;
#pragma unroll
            for (int e = 0; e < 2; e++) {
                int cc = 2 * qc + e;
                int lk = qrk * 4 + (cc & 3);
                int s  = cc >> 2;
                float bv = e ? bb.y : bb.x;
                dbase[lk * 4 + s]     = __uint_as_float(f2tf(o[jc][e]     + bv)); // jto=0
                dbase[lk * 4 + 2 + s] = __uint_as_float(f2tf(o[jc][e + 2] + bv)); // jto=1
            }
        }
    } else {
        // V-pack (paired j): kc_lo even, kc_hi = kc_lo+1
        int b   = rlo >> 11;
        int tok = rlo & 2047;
        int kc_lo = tok >> 3;
        int s_v   = (tok & 7) >> 2;
        int t4    = tok & 3;
        float* base = out + (size_t)(b * 8 + nb) * 131072;
#pragma unroll
        for (int jc = 0; jc < 8; jc++) {
            float2 bb = *(const float2*)&bias[n0 + jc * 8 + 2 * qc];
            size_t off = (size_t)(jc >> 1) * 128 + (jc & 1) * 2 + s_v;
#pragma unroll
            for (int e = 0; e < 2; e++) {
                int cc = 2 * qc + e;
                int lv = cc * 4 + t4;
                float bv = e ? bb.y : bb.x;
                base[(size_t)kc_lo * 512 + off + lv * 4] =
                    __uint_as_float(f2tf(o[jc][e] + bv));
                base[(size_t)(kc_lo + 1) * 512 + off + lv * 4] =
                    __uint_as_float(f2tf(o[jc][e + 2] + bv));
            }
        }
    }
}

// ---------------------------------------------------------------------------
// tf32 flash attention, smem-free, paired B-frag loads + bitmask.
// Block = (64 queries, b, h); 4 warps x 16 rows; key chunks of 64.
// ---------------------------------------------------------------------------
__global__ void __launch_bounds__(128) attn_tc_kernel(
    const float* __restrict__ Qp, const float* __restrict__ Kp,
    const float* __restrict__ Vp, const unsigned long long* __restrict__ mb,
    float* __restrict__ Mp)
{
    const int h  = blockIdx.z;
    const int b  = blockIdx.y;
    const int q0 = blockIdx.x * 64;
    const int tid  = threadIdx.x;
    const int w    = tid >> 5;
    const int lane = tid & 31;
    const int qr   = lane >> 2;
    const int qc   = lane & 3;

    const int mbq = b * 128 + (q0 >> 4) + w;

    // ---- Q fragments: 8 x LDG.128, scale by rsqrt(64) ----
    uint32_t qa[8][4];
    {
        const float* qb = Qp + (size_t)mbq * 8192 + h * 1024 + lane * 4;
#pragma unroll
        for (int dd = 0; dd < 8; dd++) {
            float4 a4 = *(const float4*)(qb + dd * 128);
            qa[dd][0] = __float_as_uint(a4.x * 0.125f);
            qa[dd][1] = __float_as_uint(a4.y * 0.125f);
            qa[dd][2] = __float_as_uint(a4.z * 0.125f);
            qa[dd][3] = __float_as_uint(a4.w * 0.125f);
        }
    }

    float o[8][4];
#pragma unroll
    for (int j = 0; j < 8; j++)
#pragma unroll
        for (int u = 0; u < 4; u++) o[j][u] = 0.f;
    float m_lo = -INFINITY, m_hi = -INFINITY;
    float l_lo = 0.f, l_hi = 0.f;

    const int rlo = w * 16 + qr;
    const int rhi = rlo + 8;
    const unsigned long long* mb_lo = mb + (size_t)(b * Sx + q0 + rlo) * 32;
    const unsigned long long* mb_hi = mb + (size_t)(b * Sx + q0 + rhi) * 32;

    const size_t bh = (size_t)(b * 8 + h);
    const float* kbase = Kp + bh * 131072 + lane * 4;
    const float* vbase = Vp + bh * 131072 + lane * 4;

    const int srcA = (qr << 2) + (qc >> 1);
    const int srcB = srcA + 2;
    const bool esel = (qc & 1);
    const int bidx0 = 2 * qc;   // bit index base within each j-byte

    for (int t0 = 0; t0 < Sx; t0 += 64) {
        const int jtp0 = t0 >> 4;
        const int jt0  = t0 >> 3;

        // ---- S = Q K^T : 32 LDG.128 for 64 mmas ----
        float s[8][4];
#pragma unroll
        for (int j = 0; j < 8; j++)
#pragma unroll
            for (int u = 0; u < 4; u++) s[j][u] = 0.f;
#pragma unroll
        for (int dd = 0; dd < 8; dd++) {
            const float* kd = kbase + dd * 16384 + jtp0 * 128;
#pragma unroll
            for (int jp = 0; jp < 4; jp++) {
                float4 kv = *(const float4*)(kd + jp * 128);
                mma_tf32(s[jp * 2],     qa[dd],
                         __float_as_uint(kv.x), __float_as_uint(kv.y));
                mma_tf32(s[jp * 2 + 1], qa[dd],
                         __float_as_uint(kv.z), __float_as_uint(kv.w));
            }
        }

        // ---- mask (bitwords) + row max ----
        unsigned long long wlo = mb_lo[t0 >> 6];
        unsigned long long whi = mb_hi[t0 >> 6];
        float rmax_lo = -INFINITY, rmax_hi = -INFINITY;
#pragma unroll
        for (int j = 0; j < 8; j++) {
            int idx = j * 8 + bidx0;
            s[j][0] = ((wlo >> idx) & 1ull)       ? s[j][0] : -INFINITY;
            s[j][1] = ((wlo >> (idx + 1)) & 1ull) ? s[j][1] : -INFINITY;
            s[j][2] = ((whi >> idx) & 1ull)       ? s[j][2] : -INFINITY;
            s[j][3] = ((whi >> (idx + 1)) & 1ull) ? s[j][3] : -INFINITY;
            rmax_lo = fmaxf(rmax_lo, fmaxf(s[j][0], s[j][1]));
            rmax_hi = fmaxf(rmax_hi, fmaxf(s[j][2], s[j][3]));
        }
        rmax_lo = fmaxf(rmax_lo, __shfl_xor_sync(0xffffffff, rmax_lo, 1));
        rmax_lo = fmaxf(rmax_lo, __shfl_xor_sync(0xffffffff, rmax_lo, 2));
        rmax_hi = fmaxf(rmax_hi, __shfl_xor_sync(0xffffffff, rmax_hi, 1));
        rmax_hi = fmaxf(rmax_hi, __shfl_xor_sync(0xffffffff, rmax_hi, 2));

        float mn_lo = fmaxf(m_lo, rmax_lo);
        float mn_hi = fmaxf(m_hi, rmax_hi);
        float safe_lo = (mn_lo > -INFINITY) ? mn_lo : 0.f;
        float safe_hi = (mn_hi > -INFINITY) ? mn_hi : 0.f;
        float al = __expf(m_lo - safe_lo);
        float ah = __expf(m_hi - safe_hi);

        float rs_lo = 0.f, rs_hi = 0.f;
#pragma unroll
        for (int j = 0; j < 8; j++) {
            s[j][0] = __expf(s[j][0] - safe_lo);
            s[j][1] = __expf(s[j][1] - safe_lo);
            s[j][2] = __expf(s[j][2] - safe_hi);
            s[j][3] = __expf(s[j][3] - safe_hi);
            rs_lo += s[j][0] + s[j][1];
            rs_hi += s[j][2] + s[j][3];
        }
        rs_lo += __shfl_xor_sync(0xffffffff, rs_lo, 1);
        rs_lo += __shfl_xor_sync(0xffffffff, rs_lo, 2);
        rs_hi += __shfl_xor_sync(0xffffffff, rs_hi, 1);
        rs_hi += __shfl_xor_sync(0xffffffff, rs_hi, 2);

        l_lo = l_lo * al + rs_lo;
        l_hi = l_hi * ah + rs_hi;
        m_lo = mn_lo;
        m_hi = mn_hi;

#pragma unroll
        for (int j = 0; j < 8; j++) {
            o[j][0] *= al; o[j][1] *= al;
            o[j][2] *= ah; o[j][3] *= ah;
        }

        // ---- O += P V : shuffle C->A frag, paired V loads ----
#pragma unroll
        for (int kc = 0; kc < 8; kc++) {
            float t0v = __shfl_sync(0xffffffffu, s[kc][0], srcA);
            float t1v = __shfl_sync(0xffffffffu, s[kc][1], srcA);
            float t2v = __shfl_sync(0xffffffffu, s[kc][2], srcA);
            float t3v = __shfl_sync(0xffffffffu, s[kc][3], srcA);
            float u0v = __shfl_sync(0xffffffffu, s[kc][0], srcB);
            float u1v = __shfl_sync(0xffffffffu, s[kc][1], srcB);
            float u2v = __shfl_sync(0xffffffffu, s[kc][2], srcB);
            float u3v = __shfl_sync(0xffffffffu, s[kc][3], srcB);
            uint32_t a[4];
            a[0] = f2tf(esel ? t1v : t0v);
            a[1] = f2tf(esel ? t3v : t2v);
            a[2] = f2tf(esel ? u1v : u0v);
            a[3] = f2tf(esel ? u3v : u2v);
            const float* vd = vbase + (size_t)(jt0 + kc) * 512;
#pragma unroll
            for (int jp = 0; jp < 4; jp++) {
                float4 vv = *(const float4*)(vd + jp * 128);
                mma_tf32(o[jp * 2],     a,
                         __float_as_uint(vv.x), __float_as_uint(vv.y));
                mma_tf32(o[jp * 2 + 1], a,
                         __float_as_uint(vv.z), __float_as_uint(vv.w));
            }
        }
    }

    // ---- epilogue: normalize, write msgs in A-pack tf32 ----
    float il_lo = (l_lo > 0.f) ? (1.0f / l_lo) : 0.f;
    float il_hi = (l_hi > 0.f) ? (1.0f / l_hi) : 0.f;
#pragma unroll
    for (int jc = 0; jc < 8; jc++) {
        float* base = Mp + (size_t)(mbq * 64 + h * 8 + jc) * 128;
#pragma unroll
        for (int e = 0; e < 2; e++) {
            int cc = 2 * qc + e;
            int la = qr * 4 + (cc & 3);
            int ix = (cc >> 2) << 1;
            base[la * 4 + ix]     = __uint_as_float(f2tf(o[jc][e]     * il_lo));
            base[la * 4 + ix + 1] = __uint_as_float(f2tf(o[jc][e + 2] * il_hi));
        }
    }
}

// ---------------------------------------------------------------------------
extern "C" void kernel_launch(void* const* d_in, const int* in_sizes, int n_in,
                              void* d_out, int out_size)
{
    (void)in_sizes; (void)n_in; (void)out_size;
    const float* x    = (const float*)d_in[0];
    const float* mask = (const float*)d_in[1];
    const float* Wq   = (const float*)d_in[2];
    const float* Wk   = (const float*)d_in[3];
    const float* Wv   = (const float*)d_in[4];
    const float* bq   = (const float*)d_in[5];
    const float* bk   = (const float*)d_in[6];
    const float* bv   = (const float*)d_in[7];
    const float* Wo   = (const float*)d_in[8];
    const float* bo   = (const float*)d_in[9];
    float* out = (float*)d_out;

    float *xp, *qp, *kp, *vp, *mp, *wqp, *wkp, *wvp, *wop;
    unsigned long long* mbp;
    cudaGetSymbolAddress((void**)&xp,  g_xp);
    cudaGetSymbolAddress((void**)&qp,  g_q);
    cudaGetSymbolAddress((void**)&kp,  g_k);
    cudaGetSymbolAddress((void**)&vp,  g_v);
    cudaGetSymbolAddress((void**)&mp,  g_m);
    cudaGetSymbolAddress((void**)&wqp, g_wq);
    cudaGetSymbolAddress((void**)&wkp, g_wk);
    cudaGetSymbolAddress((void**)&wvp, g_wv);
    cudaGetSymbolAddress((void**)&wop, g_wo);
    cudaGetSymbolAddress((void**)&mbp, g_mb);

    prep_x_kernel<<<8192, 256>>>(x, xp);
    prep_w_kernel<<<256, 256>>>(Wq, wqp);
    prep_w_kernel<<<256, 256>>>(Wk, wkp);
    prep_w_kernel<<<256, 256>>>(Wv, wvp);
    prep_w_kernel<<<256, 256>>>(Wo, wop);
    prep_mask_kernel<<<2048, 256>>>(mask, mbp);

    dim3 gg(8, 256);
    gemm_tc_kernel<3><<<gg, 128>>>(xp, wqp, bq, qp);   // Q -> A-pack
    gemm_tc_kernel<1><<<gg, 128>>>(xp, wkp, bk, kp);   // K -> paired B-frag pack
    gemm_tc_kernel<2><<<gg, 128>>>(xp, wvp, bv, vp);   // V -> paired B-frag pack

    dim3 ga(Sx / 64, Bx, Hx);   // (32, 8, 8)
    attn_tc_kernel<<<ga, 128>>>(qp, kp, vp, mbp, mp);

    gemm_tc_kernel<0><<<gg, 128>>>(mp, wop, bo, out);  // final projection
}